// round 9
// baseline (speedup 1.0000x reference)
#include <cuda_runtime.h>

typedef unsigned long long u64;

#define HSZ 32
#define TSZ 4096
#define BSZ 4096
#define TPR 8                  // threads per batch row (4 W_hh rows each)
#define TPB 224                // 7 warps -> 28 rows per block -> 147 blocks, 1/SM
#define RPB (TPB / TPR)        // 28
#define HSTRIDE 36             // floats per h row buffer: 32 + 4 pad (bank skew)

__device__ __forceinline__ u64 pack2(float lo, float hi) {
    u64 r;
    asm("mov.b64 %0, {%1, %2};"
        : "=l"(r) : "r"(__float_as_uint(lo)), "r"(__float_as_uint(hi)));
    return r;
}
__device__ __forceinline__ float2 unpack2(u64 v) {
    unsigned lo, hi;
    asm("mov.b64 {%0, %1}, %2;" : "=r"(lo), "=r"(hi) : "l"(v));
    return make_float2(__uint_as_float(lo), __uint_as_float(hi));
}
// Packed fp32x2 FMA (sm_103a FFMA2): 2 MACs per lane per issue, rt=2.
__device__ __forceinline__ u64 ffma2(u64 a, u64 b, u64 c) {
    u64 d;
    asm("fma.rn.f32x2 %0, %1, %2, %3;" : "=l"(d) : "l"(a), "l"(b), "l"(c));
    return d;
}
// LDS.128 straight into two u64 operand pairs (no repack movs).
__device__ __forceinline__ void lds_v2u64(u64& a, u64& b, unsigned addr) {
    asm volatile("ld.shared.v2.u64 {%0, %1}, [%2];"
                 : "=l"(a), "=l"(b) : "r"(addr));
}
__device__ __forceinline__ void sts_v4f32(unsigned addr, float a, float b,
                                          float c, float d) {
    asm volatile("st.shared.v4.f32 [%0], {%1, %2, %3, %4};"
                 :: "r"(addr), "f"(a), "f"(b), "f"(c), "f"(d));
}

__global__ void __launch_bounds__(TPB, 1)
rnn_fused_kernel(const float* __restrict__ x,
                 const float* __restrict__ h_init,
                 const float* __restrict__ W_ih,
                 const float* __restrict__ W_hh,
                 const float* __restrict__ b_ih,
                 const float* __restrict__ b_hh,
                 const float* __restrict__ W_reg,
                 const float* __restrict__ b_reg,
                 float* __restrict__ out)
{
    __shared__ float hbuf[2][RPB][HSTRIDE];

    const int tid  = threadIdx.x;
    const int gtid = blockIdx.x * TPB + tid;
    const int b    = gtid >> 3;          // batch row (8 threads per row)
    if (b >= BSZ) return;                // warp-uniform exit
    const int s    = tid & 7;            // sub-lane: owns output rows 4s..4s+3
    const int r    = tid >> 3;           // row index within block

    // --- W_hh rows 4s..4s+3 as packed k-pairs: w2[jj][q] = (W[j][2q], W[j][2q+1])
    u64 w2[4][16];
    const u64* Whh2 = reinterpret_cast<const u64*>(W_hh);
#pragma unroll
    for (int jj = 0; jj < 4; jj++)
#pragma unroll
        for (int q = 0; q < 16; q++)
            w2[jj][q] = Whh2[(4 * s + jj) * 16 + q];

    // --- acc init constants: lo gets bias + even-k, hi gets x*W_ih + odd-k
    u64 wi2[4], cb2[4];
#pragma unroll
    for (int jj = 0; jj < 4; jj++) {
        int j = 4 * s + jj;
        cb2[jj] = pack2(b_ih[j] + b_hh[j], 0.0f);
        wi2[jj] = pack2(0.0f, W_ih[j]);      // W_ih is (H, I=1)
    }

    // --- h state: full 32-vector as 16 packed pairs in every thread
    u64 h2[16];
    const u64* hini = reinterpret_cast<const u64*>(h_init) + (size_t)b * (HSZ / 2);
#pragma unroll
    for (int q = 0; q < 16; q++) h2[q] = hini[q];

    // --- shared-memory broadcast addresses (double-buffered, warp-private)
    unsigned sbase = (unsigned)__cvta_generic_to_shared(&hbuf[0][0][0]);
    unsigned rd0 = sbase + (unsigned)((0 * RPB + r) * HSTRIDE * 4);
    unsigned rd1 = sbase + (unsigned)((1 * RPB + r) * HSTRIDE * 4);
    unsigned wr0 = rd0 + (unsigned)(s * 16);
    unsigned wr1 = rd1 + (unsigned)(s * 16);

    const float4* x4 = reinterpret_cast<const float4*>(x + (size_t)b * TSZ);

#define RNN_STEP(XT, WRA, RDA)                                               \
    {                                                                        \
        u64 xs = pack2((XT), (XT));                                          \
        u64 a0 = ffma2(xs, wi2[0], cb2[0]);                                  \
        u64 a1 = ffma2(xs, wi2[1], cb2[1]);                                  \
        u64 a2 = ffma2(xs, wi2[2], cb2[2]);                                  \
        u64 a3 = ffma2(xs, wi2[3], cb2[3]);                                  \
        _Pragma("unroll")                                                    \
        for (int q = 0; q < 16; q++) {                                       \
            a0 = ffma2(h2[q], w2[0][q], a0);                                 \
            a1 = ffma2(h2[q], w2[1][q], a1);                                 \
            a2 = ffma2(h2[q], w2[2][q], a2);                                 \
            a3 = ffma2(h2[q], w2[3][q], a3);                                 \
        }                                                                    \
        float2 p0 = unpack2(a0), p1 = unpack2(a1);                           \
        float2 p2 = unpack2(a2), p3 = unpack2(a3);                           \
        float v0 = fmaxf(p0.x + p0.y, 0.0f);                                 \
        float v1 = fmaxf(p1.x + p1.y, 0.0f);                                 \
        float v2 = fmaxf(p2.x + p2.y, 0.0f);                                 \
        float v3 = fmaxf(p3.x + p3.y, 0.0f);                                 \
        sts_v4f32((WRA), v0, v1, v2, v3);                                    \
        __syncwarp();                                                        \
        _Pragma("unroll")                                                    \
        for (int q = 0; q < 8; q++)                                          \
            lds_v2u64(h2[2 * q], h2[2 * q + 1], (RDA) + (unsigned)(q * 16)); \
    }

    // Software-pipelined x stream: issue next iteration's DRAM load (~600 cyc
    // latency) one 4-step group (~1300 cyc) ahead of its first use.
    float4 xv = __ldg(x4);
    for (int t4 = 0; t4 < TSZ / 4; t4++) {
        int tn = t4 + 1;
        if (tn > TSZ / 4 - 1) tn = TSZ / 4 - 1;   // clamp (branchless IMNMX)
        float4 xn = __ldg(x4 + tn);
        RNN_STEP(xv.x, wr0, rd0)
        RNN_STEP(xv.y, wr1, rd1)
        RNN_STEP(xv.z, wr0, rd0)
        RNN_STEP(xv.w, wr1, rd1)
        xv = xn;
    }
#undef RNN_STEP

    // --- final projection: out[b] = h . W_reg[0,:] + b_reg (all lanes hold full h)
    if (s == 0) {
        const u64* Wr2 = reinterpret_cast<const u64*>(W_reg);
        u64 acc = pack2(0.0f, 0.0f);
#pragma unroll
        for (int q = 0; q < 16; q++)
            acc = ffma2(h2[q], Wr2[q], acc);
        float2 pr = unpack2(acc);
        out[b] = pr.x + pr.y + b_reg[0];
    }
}

extern "C" void kernel_launch(void* const* d_in, const int* in_sizes, int n_in,
                              void* d_out, int out_size)
{
    const float* x      = (const float*)d_in[0];
    const float* h_init = (const float*)d_in[1];
    const float* W_ih   = (const float*)d_in[2];
    const float* W_hh   = (const float*)d_in[3];
    const float* b_ih   = (const float*)d_in[4];
    const float* b_hh   = (const float*)d_in[5];
    const float* W_reg  = (const float*)d_in[6];
    const float* b_reg  = (const float*)d_in[7];
    float* out = (float*)d_out;

    const int total  = BSZ * TPR;                     // 32768 threads
    const int blocks = (total + TPB - 1) / TPB;       // 147
    rnn_fused_kernel<<<blocks, TPB>>>(x, h_init, W_ih, W_hh,
                                      b_ih, b_hh, W_reg, b_reg, out);
}

// round 10
// speedup vs baseline: 1.0066x; 1.0066x over previous
#include <cuda_runtime.h>

typedef unsigned long long u64;

#define HSZ 32
#define TSZ 4096
#define BSZ 4096
#define TPR 8                  // threads per batch row (4 W_hh rows each)
#define TPB 224                // 7 warps -> 28 rows per block -> 147 blocks, 1/SM
#define RPB (TPB / TPR)        // 28
#define HSTRIDE 36             // floats per h row buffer: 32 + 4 pad (bank skew)

__device__ __forceinline__ u64 pack2(float lo, float hi) {
    u64 r;
    asm("mov.b64 %0, {%1, %2};"
        : "=l"(r) : "r"(__float_as_uint(lo)), "r"(__float_as_uint(hi)));
    return r;
}
__device__ __forceinline__ float2 unpack2(u64 v) {
    unsigned lo, hi;
    asm("mov.b64 {%0, %1}, %2;" : "=r"(lo), "=r"(hi) : "l"(v));
    return make_float2(__uint_as_float(lo), __uint_as_float(hi));
}
// Packed fp32x2 FMA (sm_103a FFMA2): 2 MACs per lane per issue, rt=2.
__device__ __forceinline__ u64 ffma2(u64 a, u64 b, u64 c) {
    u64 d;
    asm("fma.rn.f32x2 %0, %1, %2, %3;" : "=l"(d) : "l"(a), "l"(b), "l"(c));
    return d;
}
// LDS.128 straight into two u64 operand pairs (no repack movs).
__device__ __forceinline__ void lds_v2u64(u64& a, u64& b, unsigned addr) {
    asm volatile("ld.shared.v2.u64 {%0, %1}, [%2];"
                 : "=l"(a), "=l"(b) : "r"(addr));
}
__device__ __forceinline__ void sts_v4f32(unsigned addr, float a, float b,
                                          float c, float d) {
    asm volatile("st.shared.v4.f32 [%0], {%1, %2, %3, %4};"
                 :: "r"(addr), "f"(a), "f"(b), "f"(c), "f"(d));
}

__global__ void __launch_bounds__(TPB, 1)
rnn_fused_kernel(const float* __restrict__ x,
                 const float* __restrict__ h_init,
                 const float* __restrict__ W_ih,
                 const float* __restrict__ W_hh,
                 const float* __restrict__ b_ih,
                 const float* __restrict__ b_hh,
                 const float* __restrict__ W_reg,
                 const float* __restrict__ b_reg,
                 float* __restrict__ out)
{
    __shared__ float hbuf[2][RPB][HSTRIDE];

    const int tid  = threadIdx.x;
    const int gtid = blockIdx.x * TPB + tid;
    const int b    = gtid >> 3;          // batch row (8 threads per row)
    if (b >= BSZ) return;                // warp-uniform exit
    const int s    = tid & 7;            // sub-lane: owns output rows 4s..4s+3
    const int r    = tid >> 3;           // row index within block

    // --- W_hh rows 4s..4s+3 as packed k-pairs: w2[jj][q] = (W[j][2q], W[j][2q+1])
    u64 w2[4][16];
    const u64* Whh2 = reinterpret_cast<const u64*>(W_hh);
#pragma unroll
    for (int jj = 0; jj < 4; jj++)
#pragma unroll
        for (int q = 0; q < 16; q++)
            w2[jj][q] = Whh2[(4 * s + jj) * 16 + q];

    // --- acc init constants: lo gets bias + even-k, hi gets x*W_ih + odd-k
    u64 wi2[4], cb2[4];
#pragma unroll
    for (int jj = 0; jj < 4; jj++) {
        int j = 4 * s + jj;
        cb2[jj] = pack2(b_ih[j] + b_hh[j], 0.0f);
        wi2[jj] = pack2(0.0f, W_ih[j]);      // W_ih is (H, I=1)
    }

    // --- h state: full 32-vector as 16 packed pairs in every thread
    u64 h2[16];
    const u64* hini = reinterpret_cast<const u64*>(h_init) + (size_t)b * (HSZ / 2);
#pragma unroll
    for (int q = 0; q < 16; q++) h2[q] = hini[q];

    // --- shared-memory broadcast addresses (double-buffered, warp-private)
    unsigned sbase = (unsigned)__cvta_generic_to_shared(&hbuf[0][0][0]);
    unsigned rd0 = sbase + (unsigned)((0 * RPB + r) * HSTRIDE * 4);
    unsigned rd1 = sbase + (unsigned)((1 * RPB + r) * HSTRIDE * 4);
    unsigned wr0 = rd0 + (unsigned)(s * 16);
    unsigned wr1 = rd1 + (unsigned)(s * 16);

    const float4* x4 = reinterpret_cast<const float4*>(x + (size_t)b * TSZ);

#define RNN_STEP(XT, WRA, RDA)                                               \
    {                                                                        \
        u64 xs = pack2((XT), (XT));                                          \
        u64 a0 = ffma2(xs, wi2[0], cb2[0]);                                  \
        u64 a1 = ffma2(xs, wi2[1], cb2[1]);                                  \
        u64 a2 = ffma2(xs, wi2[2], cb2[2]);                                  \
        u64 a3 = ffma2(xs, wi2[3], cb2[3]);                                  \
        _Pragma("unroll")                                                    \
        for (int q = 0; q < 16; q++) {                                       \
            a0 = ffma2(h2[q], w2[0][q], a0);                                 \
            a1 = ffma2(h2[q], w2[1][q], a1);                                 \
            a2 = ffma2(h2[q], w2[2][q], a2);                                 \
            a3 = ffma2(h2[q], w2[3][q], a3);                                 \
        }                                                                    \
        float2 p0 = unpack2(a0), p1 = unpack2(a1);                           \
        float2 p2 = unpack2(a2), p3 = unpack2(a3);                           \
        float v0 = fmaxf(p0.x + p0.y, 0.0f);                                 \
        float v1 = fmaxf(p1.x + p1.y, 0.0f);                                 \
        float v2 = fmaxf(p2.x + p2.y, 0.0f);                                 \
        float v3 = fmaxf(p3.x + p3.y, 0.0f);                                 \
        sts_v4f32((WRA), v0, v1, v2, v3);                                    \
        __syncwarp();                                                        \
        _Pragma("unroll")                                                    \
        for (int q = 0; q < 8; q++)                                          \
            lds_v2u64(h2[2 * q], h2[2 * q + 1], (RDA) + (unsigned)(q * 16)); \
    }

    // Software-pipelined x stream: issue next iteration's DRAM load (~600 cyc
    // latency) one 4-step group (~1300 cyc) ahead of its first use.
    float4 xv = __ldg(x4);
    for (int t4 = 0; t4 < TSZ / 4; t4++) {
        int tn = t4 + 1;
        if (tn > TSZ / 4 - 1) tn = TSZ / 4 - 1;   // clamp (branchless IMNMX)
        float4 xn = __ldg(x4 + tn);
        RNN_STEP(xv.x, wr0, rd0)
        RNN_STEP(xv.y, wr1, rd1)
        RNN_STEP(xv.z, wr0, rd0)
        RNN_STEP(xv.w, wr1, rd1)
        xv = xn;
    }
#undef RNN_STEP

    // --- final projection: out[b] = h . W_reg[0,:] + b_reg (all lanes hold full h)
    if (s == 0) {
        const u64* Wr2 = reinterpret_cast<const u64*>(W_reg);
        u64 acc = pack2(0.0f, 0.0f);
#pragma unroll
        for (int q = 0; q < 16; q++)
            acc = ffma2(h2[q], Wr2[q], acc);
        float2 pr = unpack2(acc);
        out[b] = pr.x + pr.y + b_reg[0];
    }
}

extern "C" void kernel_launch(void* const* d_in, const int* in_sizes, int n_in,
                              void* d_out, int out_size)
{
    const float* x      = (const float*)d_in[0];
    const float* h_init = (const float*)d_in[1];
    const float* W_ih   = (const float*)d_in[2];
    const float* W_hh   = (const float*)d_in[3];
    const float* b_ih   = (const float*)d_in[4];
    const float* b_hh   = (const float*)d_in[5];
    const float* W_reg  = (const float*)d_in[6];
    const float* b_reg  = (const float*)d_in[7];
    float* out = (float*)d_out;

    const int total  = BSZ * TPR;                     // 32768 threads
    const int blocks = (total + TPB - 1) / TPB;       // 147
    rnn_fused_kernel<<<blocks, TPB>>>(x, h_init, W_ih, W_hh,
                                      b_ih, b_hh, W_reg, b_reg, out);
}